// round 14
// baseline (speedup 1.0000x reference)
#include <cuda_runtime.h>
#include <cuda_bf16.h>
#include <cstdint>

// Problem constants
#define NB   4
#define CC   128
#define HH   64
#define WW   64
#define LL   (HH*WW)          // 4096
#define NL   (NB*LL)          // 16384
#define GG   4
#define KK   9
#define CG   32               // CC/GG
#define OM   108              // G*3*K
#define VOST 256              // combined value+om row stride
#define EPSF 1e-5f
#define LDA  136              // padded bf16 row length (272B -> conflict-free ldmatrix)

__device__ __forceinline__ uint32_t smem_to_u32(const void* p) {
    uint32_t a;
    asm("{ .reg .u64 t; cvta.to.shared.u64 t, %1; cvt.u32.u64 %0, t; }" : "=r"(a) : "l"(p));
    return a;
}

__device__ __forceinline__ void ldm_x4(uint32_t addr, uint32_t& r0, uint32_t& r1,
                                       uint32_t& r2, uint32_t& r3) {
    asm volatile("ldmatrix.sync.aligned.m8n8.x4.shared.b16 {%0,%1,%2,%3}, [%4];"
                 : "=r"(r0), "=r"(r1), "=r"(r2), "=r"(r3) : "r"(addr));
}

__device__ __forceinline__ void mma16816(float* d, const uint32_t* a, const uint32_t* b) {
    asm volatile(
        "mma.sync.aligned.m16n8k16.row.col.f32.bf16.bf16.f32 "
        "{%0,%1,%2,%3}, {%4,%5,%6,%7}, {%8,%9}, {%0,%1,%2,%3};"
        : "+f"(d[0]), "+f"(d[1]), "+f"(d[2]), "+f"(d[3])
        : "r"(a[0]), "r"(a[1]), "r"(a[2]), "r"(a[3]), "r"(b[0]), "r"(b[1]));
}

// ---------------- scratch (device globals; no allocation allowed) ----------------
__device__ float g_t   [NL*CC];
__device__ float g_vo  [NL*VOST];
__device__ float g_samp[NL*CC];
__device__ float g_d   [NL*CC];
__device__ float g_part[2*128*CC];
__device__ float g_scale[CC];
__device__ float g_shift[CC];
__device__ float g_bcat[VOST];
__device__ __nv_bfloat16 g_WcatT_hi[VOST*CC];  // [n=256][k=128] = {Wv|Wom}^T
__device__ __nv_bfloat16 g_WcatT_lo[VOST*CC];
__device__ __nv_bfloat16 g_WoT_hi[CC*CC];      // [n][k] = Wo[k][n]
__device__ __nv_bfloat16 g_WoT_lo[CC*CC];
__device__ __nv_bfloat16 g_Wc_hi[CC*CC];       // [o][c] = Wc as-is
__device__ __nv_bfloat16 g_Wc_lo[CC*CC];

// ---------------- weight packing + bf16 split (once per launch) ----------------
__device__ __forceinline__ void split_store(float v, __nv_bfloat16* hi, __nv_bfloat16* lo, int idx) {
    __nv_bfloat16 h = __float2bfloat16_rn(v);
    hi[idx] = h;
    lo[idx] = __float2bfloat16_rn(v - __bfloat162float(h));
}

__global__ void pack_w_kernel(const float* __restrict__ Wv, const float* __restrict__ bv,
                              const float* __restrict__ Wom, const float* __restrict__ bom,
                              const float* __restrict__ Wo, const float* __restrict__ Wc,
                              float* __restrict__ bcat) {
    int n = blockIdx.x;    // 0..255
    int k = threadIdx.x;   // 0..127
    float v = 0.f;
    if (n < CC)           v = Wv[k * CC + n];
    else if (n < CC + OM) v = Wom[k * OM + (n - CC)];
    split_store(v, g_WcatT_hi, g_WcatT_lo, n * CC + k);
    if (n < CC) {
        split_store(Wo[k * CC + n], g_WoT_hi, g_WoT_lo, n * CC + k);
        split_store(Wc[n * CC + k], g_Wc_hi,  g_Wc_lo,  n * CC + k);
    }
    if (k == 0) {
        float b = 0.f;
        if (n < CC)           b = bv[n];
        else if (n < CC + OM) b = bom[n - CC];
        bcat[n] = b;
    }
}

// ---------------- transposes ----------------
__global__ void t_c2l_kernel(const float* __restrict__ in, float* __restrict__ out) {
    __shared__ float tile[32][33];
    int n = blockIdx.z, l0 = blockIdx.x * 32, c0 = blockIdx.y * 32;
    const float* ip = in  + (size_t)n * CC * LL;
    float*       op = out + (size_t)n * CC * LL;
    int tx = threadIdx.x, ty = threadIdx.y;
    #pragma unroll
    for (int j = 0; j < 32; j += 8)
        tile[ty + j][tx] = ip[(size_t)(c0 + ty + j) * LL + l0 + tx];
    __syncthreads();
    #pragma unroll
    for (int j = 0; j < 32; j += 8)
        op[(size_t)(l0 + ty + j) * CC + c0 + tx] = tile[tx][ty + j];
}

__global__ void t_l2c_kernel(const float* __restrict__ in, float* __restrict__ out) {
    __shared__ float tile[32][33];
    int n = blockIdx.z, l0 = blockIdx.x * 32, c0 = blockIdx.y * 32;
    const float* ip = in  + (size_t)n * CC * LL;
    float*       op = out + (size_t)n * CC * LL;
    int tx = threadIdx.x, ty = threadIdx.y;
    #pragma unroll
    for (int j = 0; j < 32; j += 8)
        tile[ty + j][tx] = ip[(size_t)(l0 + ty + j) * CC + c0 + tx];
    __syncthreads();
    #pragma unroll
    for (int j = 0; j < 32; j += 8)
        op[(size_t)(c0 + ty + j) * LL + l0 + tx] = tile[tx][ty + j];
}

// ---------------- HMMA GEMM: C[M,N] = A[M,128] @ B^T (+bias) ----------------
// bf16 split: D = Ahi*Bhi + Alo*Bhi + Ahi*Blo, fp32 accumulate.
// CTA = 128x128 tile, 256 threads (8 warps, 2M x 4N), warp = 64x32.
// Register-double-buffered fragments across k-steps.
#define LOAD_FRAGS(k0, buf)                                                             \
    do {                                                                                \
        _Pragma("unroll")                                                               \
        for (int mi = 0; mi < 4; mi++) {                                                \
            uint32_t off = (uint32_t)((wm + mi * 16 + a_r) * LDA + (k0) + a_c) * 2;     \
            ldm_x4(baseA + off,        ah[buf][mi][0], ah[buf][mi][1],                  \
                                       ah[buf][mi][2], ah[buf][mi][3]);                 \
            ldm_x4(baseA + dAlo + off, al[buf][mi][0], al[buf][mi][1],                  \
                                       al[buf][mi][2], al[buf][mi][3]);                 \
        }                                                                               \
        _Pragma("unroll")                                                               \
        for (int p = 0; p < 2; p++) {                                                   \
            uint32_t off = (uint32_t)((wn + p * 16 + b_r) * LDA + (k0) + b_c) * 2;      \
            ldm_x4(baseB + off,        bh[buf][2*p][0], bh[buf][2*p][1],                \
                                       bh[buf][2*p+1][0], bh[buf][2*p+1][1]);           \
            ldm_x4(baseB + dBlo + off, bl[buf][2*p][0], bl[buf][2*p][1],                \
                                       bl[buf][2*p+1][0], bl[buf][2*p+1][1]);           \
        }                                                                               \
    } while (0)

__global__ __launch_bounds__(256, 1)
void mma_gemm_kernel(const float* __restrict__ A,
                     const __nv_bfloat16* __restrict__ Bhi,
                     const __nv_bfloat16* __restrict__ Blo,
                     const float* __restrict__ bias,
                     float* __restrict__ C, int ldc,
                     const float* __restrict__ ascale, const float* __restrict__ ashift,
                     float* __restrict__ part) {
    extern __shared__ __nv_bfloat16 sm[];
    __nv_bfloat16* sAh = sm;                 // [128][LDA]
    __nv_bfloat16* sAl = sAh + 128 * LDA;
    __nv_bfloat16* sBh = sAl + 128 * LDA;
    __nv_bfloat16* sBl = sBh + 128 * LDA;

    int tid = threadIdx.x;
    int bm0 = blockIdx.y * 128;
    int bn0 = blockIdx.x * 128;

    // ---- stage A: fp32 -> bf16 hi/lo (+ optional BN+ReLU) ----
    {
        int row = tid >> 1, kh = (tid & 1) * 64;
        const float* ar = A + (size_t)(bm0 + row) * 128 + kh;
        __nv_bfloat16* dh = sAh + row * LDA + kh;
        __nv_bfloat16* dl = sAl + row * LDA + kh;
        #pragma unroll
        for (int i = 0; i < 64; i += 8) {
            float v[8];
            *(float4*)&v[0] = *(const float4*)(ar + i);
            *(float4*)&v[4] = *(const float4*)(ar + i + 4);
            if (ascale) {
                #pragma unroll
                for (int j = 0; j < 8; j++)
                    v[j] = fmaxf(fmaf(v[j], ascale[kh + i + j], ashift[kh + i + j]), 0.f);
            }
            uint32_t h[4], l[4];
            #pragma unroll
            for (int p = 0; p < 4; p++) {
                __nv_bfloat16 h0 = __float2bfloat16_rn(v[2 * p]);
                __nv_bfloat16 h1 = __float2bfloat16_rn(v[2 * p + 1]);
                float l0 = v[2 * p] - __bfloat162float(h0);
                float l1 = v[2 * p + 1] - __bfloat162float(h1);
                __nv_bfloat162 hp; hp.x = h0; hp.y = h1;
                __nv_bfloat162 lp; lp.x = __float2bfloat16_rn(l0); lp.y = __float2bfloat16_rn(l1);
                h[p] = *reinterpret_cast<uint32_t*>(&hp);
                l[p] = *reinterpret_cast<uint32_t*>(&lp);
            }
            *(uint4*)(dh + i) = make_uint4(h[0], h[1], h[2], h[3]);
            *(uint4*)(dl + i) = make_uint4(l[0], l[1], l[2], l[3]);
        }
    }
    // ---- stage B: bf16 copy ----
    {
        int row = tid >> 1, kh = (tid & 1) * 64;
        const uint4* bh4 = (const uint4*)(Bhi + (size_t)(bn0 + row) * 128 + kh);
        const uint4* bl4 = (const uint4*)(Blo + (size_t)(bn0 + row) * 128 + kh);
        uint4* dh = (uint4*)(sBh + row * LDA + kh);
        uint4* dl = (uint4*)(sBl + row * LDA + kh);
        #pragma unroll
        for (int i = 0; i < 8; i++) { dh[i] = bh4[i]; dl[i] = bl4[i]; }
    }
    __syncthreads();

    int wid = tid >> 5, lane = tid & 31;
    int wm = (wid >> 2) * 64;      // warp M origin within tile
    int wn = (wid & 3) * 32;       // warp N origin within tile

    uint32_t baseA = smem_to_u32(sAh);
    uint32_t dAlo  = (uint32_t)(128 * LDA * 2);
    uint32_t baseB = smem_to_u32(sBh);
    uint32_t dBlo  = dAlo;

    int a_r = (lane & 7) + ((lane >> 3) & 1) * 8;
    int a_c = ((lane >> 4) & 1) * 8;
    int b_r = (lane & 7) + ((lane >> 4) & 1) * 8;
    int b_c = ((lane >> 3) & 1) * 8;

    float acc[4][4][4];
    #pragma unroll
    for (int i = 0; i < 4; i++)
        #pragma unroll
        for (int j = 0; j < 4; j++)
            #pragma unroll
            for (int q = 0; q < 4; q++) acc[i][j][q] = 0.f;

    // register-double-buffered fragments
    uint32_t ah[2][4][4], al[2][4][4], bh[2][4][2], bl[2][4][2];
    LOAD_FRAGS(0, 0);

    #pragma unroll
    for (int kt = 0; kt < 8; kt++) {
        int buf = kt & 1;
        if (kt < 7) LOAD_FRAGS((kt + 1) * 16, buf ^ 1);
        #pragma unroll
        for (int mi = 0; mi < 4; mi++)
            #pragma unroll
            for (int nj = 0; nj < 4; nj++) {
                mma16816(acc[mi][nj], ah[buf][mi], bh[buf][nj]);
                mma16816(acc[mi][nj], al[buf][mi], bh[buf][nj]);
                mma16816(acc[mi][nj], ah[buf][mi], bl[buf][nj]);
            }
    }

    // ---- epilogue (+bias, + optional BN partial sums) ----
    int q = lane >> 2, idx = lane & 3;
    float s[8] = {}, s2[8] = {};
    #pragma unroll
    for (int mi = 0; mi < 4; mi++) {
        int r0 = bm0 + wm + mi * 16 + q;
        #pragma unroll
        for (int nj = 0; nj < 4; nj++) {
            int c = bn0 + wn + nj * 8 + idx * 2;
            float2 v0 = make_float2(acc[mi][nj][0], acc[mi][nj][1]);
            float2 v1 = make_float2(acc[mi][nj][2], acc[mi][nj][3]);
            if (bias) {
                float2 b = *(const float2*)&bias[c];
                v0.x += b.x; v0.y += b.y; v1.x += b.x; v1.y += b.y;
            }
            if (part) {
                s[nj*2]    += v0.x + v1.x;
                s[nj*2+1]  += v0.y + v1.y;
                s2[nj*2]   = fmaf(v0.x, v0.x, fmaf(v1.x, v1.x, s2[nj*2]));
                s2[nj*2+1] = fmaf(v0.y, v0.y, fmaf(v1.y, v1.y, s2[nj*2+1]));
            }
            *(float2*)&C[(size_t)r0 * ldc + c]       = v0;
            *(float2*)&C[(size_t)(r0 + 8) * ldc + c] = v1;
        }
    }

    if (part) {
        __syncthreads();
        float* red  = (float*)sm;              // [128 cols][16 contributors]
        float* red2 = red + 2048;
        int r = q + ((wid >> 2) << 3);         // 0..15
        #pragma unroll
        for (int nj = 0; nj < 4; nj++) {
            #pragma unroll
            for (int t = 0; t < 2; t++) {
                int c = wn + nj * 8 + idx * 2 + t;
                red [c * 16 + r] = s[nj*2+t];
                red2[c * 16 + r] = s2[nj*2+t];
            }
        }
        __syncthreads();
        if (tid < 128) {
            float a0 = 0.f, a1 = 0.f;
            #pragma unroll
            for (int t = 0; t < 16; t++) { a0 += red[tid * 16 + t]; a1 += red2[tid * 16 + t]; }
            part[blockIdx.y * CC + tid]            = a0;
            part[128 * CC + blockIdx.y * CC + tid] = a1;
        }
    }
}

// ---------------- deformable sampling: 2 positions/warp, batched loads ----------------
__global__ __launch_bounds__(256)
void sample_kernel(const float* __restrict__ vo, float* __restrict__ out) {
    __shared__ float s_om[16][OM];
    int wid  = threadIdx.x >> 5;
    int lane = threadIdx.x & 31;
    int pos0 = (blockIdx.x * 8 + wid) * 2;
    int g = lane >> 3;

    const float* omp = vo + (size_t)pos0 * VOST + CC;
    #pragma unroll
    for (int i = lane; i < OM; i += 32) {
        s_om[2*wid][i]     = omp[i];
        s_om[2*wid + 1][i] = omp[VOST + i];
    }
    __syncwarp();

    int n  = pos0 >> 12;
    int l0 = pos0 & 4095;
    int h  = l0 >> 6;
    int w0 = l0 & 63;
    const float* vbase = vo + (size_t)n * (LL * VOST) + (lane << 2);
    const float* omg[2] = { &s_om[2*wid][g * 27], &s_om[2*wid + 1][g * 27] };

    float ax[2] = {}, ay[2] = {}, az[2] = {}, aw4[2] = {};

    #pragma unroll
    for (int k = 0; k < KK; k++) {
        int kdy = k / 3 - 1, kdx = k % 3 - 1;
        int   off[2][4];
        float cw[2][4];
        float mk[2];
        #pragma unroll
        for (int p = 0; p < 2; p++) {
            float offx = omg[p][2 * k];
            float offy = omg[p][2 * k + 1];
            mk[p] = omg[p][18 + k];
            float ly = (float)(h + kdy) + offy;
            float lx = (float)(w0 + p + kdx) + offx;
            float y0f = floorf(ly), x0f = floorf(lx);
            float wy = ly - y0f, wx = lx - x0f;
            int y0 = (int)y0f, x0 = (int)x0f;
            if (y0 >= 0 && y0 < HH - 1 && x0 >= 0 && x0 < WW - 1) {
                int o = (y0 << 14) + (x0 << 8);
                off[p][0] = o;
                off[p][1] = o + VOST;
                off[p][2] = o + WW * VOST;
                off[p][3] = o + WW * VOST + VOST;
                cw[p][0] = (1.f - wy) * (1.f - wx);
                cw[p][1] = (1.f - wy) * wx;
                cw[p][2] = wy * (1.f - wx);
                cw[p][3] = wy * wx;
            } else {
                #pragma unroll
                for (int c = 0; c < 4; c++) {
                    int yi = y0 + (c >> 1), xi = x0 + (c & 1);
                    float wgt = ((c >> 1) ? wy : 1.f - wy) * ((c & 1) ? wx : 1.f - wx);
                    bool valid = (yi >= 0) && (yi < HH) && (xi >= 0) && (xi < WW);
                    int yc = min(max(yi, 0), HH - 1);
                    int xc = min(max(xi, 0), WW - 1);
                    off[p][c] = (yc << 14) + (xc << 8);
                    cw[p][c]  = valid ? wgt : 0.f;
                }
            }
        }
        float4 v[2][4];
        #pragma unroll
        for (int p = 0; p < 2; p++)
            #pragma unroll
            for (int c = 0; c < 4; c++)
                v[p][c] = *(const float4*)(vbase + off[p][c]);
        #pragma unroll
        for (int p = 0; p < 2; p++) {
            float sx = 0.f, sy = 0.f, sz = 0.f, sw = 0.f;
            #pragma unroll
            for (int c = 0; c < 4; c++) {
                sx = fmaf(v[p][c].x, cw[p][c], sx);
                sy = fmaf(v[p][c].y, cw[p][c], sy);
                sz = fmaf(v[p][c].z, cw[p][c], sz);
                sw = fmaf(v[p][c].w, cw[p][c], sw);
            }
            ax[p]  = fmaf(sx, mk[p], ax[p]);
            ay[p]  = fmaf(sy, mk[p], ay[p]);
            az[p]  = fmaf(sz, mk[p], az[p]);
            aw4[p] = fmaf(sw, mk[p], aw4[p]);
        }
    }
    *(float4*)&out[(size_t)pos0 * CC + (lane << 2)]       = make_float4(ax[0], ay[0], az[0], aw4[0]);
    *(float4*)&out[(size_t)(pos0 + 1) * CC + (lane << 2)] = make_float4(ax[1], ay[1], az[1], aw4[1]);
}

// ---------------- batchnorm finalize / apply ----------------
__global__ void bn_final_kernel(const float* __restrict__ part,
                                const float* __restrict__ gamma, const float* __restrict__ beta,
                                float* __restrict__ scale, float* __restrict__ shift) {
    int c = threadIdx.x;
    float s = 0.f, s2 = 0.f;
    #pragma unroll 8
    for (int b = 0; b < 128; b++) {
        s  += part[b * CC + c];
        s2 += part[128 * CC + b * CC + c];
    }
    float mean = s * (1.f / (float)NL);
    float var  = s2 * (1.f / (float)NL) - mean * mean;
    float sc   = gamma[c] * rsqrtf(var + EPSF);
    scale[c] = sc;
    shift[c] = beta[c] - mean * sc;
}

__global__ void bn_resid_kernel(const float* __restrict__ d,
                                const float* __restrict__ scale, const float* __restrict__ shift,
                                const float* __restrict__ x, float* __restrict__ out) {
    __shared__ float tile[32][33];
    int n = blockIdx.z, l0 = blockIdx.x * 32, c0 = blockIdx.y * 32;
    int tx = threadIdx.x, ty = threadIdx.y;
    const float* xp = x + (size_t)n * CC * LL;
    #pragma unroll
    for (int j = 0; j < 32; j += 8)
        tile[ty + j][tx] = xp[(size_t)(c0 + ty + j) * LL + l0 + tx];
    __syncthreads();
    float sc = scale[c0 + tx], sh = shift[c0 + tx];
    #pragma unroll
    for (int j = 0; j < 32; j += 8) {
        size_t idx = (size_t)(n * LL + l0 + ty + j) * CC + c0 + tx;
        out[idx] = fmaf(d[idx], sc, sh) + tile[tx][ty + j];
    }
}

// ---------------- host orchestration ----------------
#define MMA_SMEM (4 * 128 * LDA * 2)   // 139264 bytes

extern "C" void kernel_launch(void* const* d_in, const int* in_sizes, int n_in,
                              void* d_out, int out_size) {
    const float* x     = (const float*)d_in[0];
    const float* Wv    = (const float*)d_in[1];
    const float* bv    = (const float*)d_in[2];
    const float* Wom   = (const float*)d_in[3];
    const float* bom   = (const float*)d_in[4];
    const float* Wo    = (const float*)d_in[5];
    const float* gamma = (const float*)d_in[6];
    const float* beta  = (const float*)d_in[7];
    const float* Wc    = (const float*)d_in[8];
    float* out = (float*)d_out;

    float *tp, *vop, *sampp, *dp, *partp, *scalep, *shiftp, *bcatp;
    __nv_bfloat16 *wcat_h, *wcat_l, *wot_h, *wot_l, *wc_h, *wc_l;
    cudaGetSymbolAddress((void**)&tp,     g_t);
    cudaGetSymbolAddress((void**)&vop,    g_vo);
    cudaGetSymbolAddress((void**)&sampp,  g_samp);
    cudaGetSymbolAddress((void**)&dp,     g_d);
    cudaGetSymbolAddress((void**)&partp,  g_part);
    cudaGetSymbolAddress((void**)&scalep, g_scale);
    cudaGetSymbolAddress((void**)&shiftp, g_shift);
    cudaGetSymbolAddress((void**)&bcatp,  g_bcat);
    cudaGetSymbolAddress((void**)&wcat_h, g_WcatT_hi);
    cudaGetSymbolAddress((void**)&wcat_l, g_WcatT_lo);
    cudaGetSymbolAddress((void**)&wot_h,  g_WoT_hi);
    cudaGetSymbolAddress((void**)&wot_l,  g_WoT_lo);
    cudaGetSymbolAddress((void**)&wc_h,   g_Wc_hi);
    cudaGetSymbolAddress((void**)&wc_l,   g_Wc_lo);

    cudaFuncSetAttribute(mma_gemm_kernel, cudaFuncAttributeMaxDynamicSharedMemorySize, MMA_SMEM);

    dim3 tBlock(32, 8);
    dim3 tGrid(LL / 32, CC / 32, NB);
    dim3 gridVO(2, NL / 128);     // N=256
    dim3 grid128(1, NL / 128);    // N=128

    // layout prep
    t_c2l_kernel<<<tGrid, tBlock>>>(x, tp);
    pack_w_kernel<<<256, 128>>>(Wv, bv, Wom, bom, Wo, Wc, bcatp);

    // ---- DCN block 1 ----
    mma_gemm_kernel<<<gridVO, 256, MMA_SMEM>>>(tp, wcat_h, wcat_l, bcatp, vop, VOST,
                                               nullptr, nullptr, nullptr);
    sample_kernel<<<NL / 16, 256>>>(vop, sampp);
    mma_gemm_kernel<<<grid128, 256, MMA_SMEM>>>(sampp, wot_h, wot_l, nullptr, dp, CC,
                                                nullptr, nullptr, partp);
    bn_final_kernel<<<1, 128>>>(partp, gamma, beta, scalep, shiftp);

    // ---- DCN block 2 (BN+ReLU fused into A staging of VO GEMM) ----
    mma_gemm_kernel<<<gridVO, 256, MMA_SMEM>>>(dp, wcat_h, wcat_l, bcatp, vop, VOST,
                                               scalep, shiftp, nullptr);
    sample_kernel<<<NL / 16, 256>>>(vop, sampp);
    mma_gemm_kernel<<<grid128, 256, MMA_SMEM>>>(sampp, wot_h, wot_l, nullptr, dp, CC,
                                                nullptr, nullptr, partp);
    bn_final_kernel<<<1, 128>>>(partp, gamma, beta, scalep, shiftp);
    bn_resid_kernel<<<tGrid, tBlock>>>(dp, scalep, shiftp, x, tp);

    // ---- final channel mix + layout ----
    mma_gemm_kernel<<<grid128, 256, MMA_SMEM>>>(tp, wc_h, wc_l, nullptr, sampp, CC,
                                                nullptr, nullptr, nullptr);
    t_l2c_kernel<<<tGrid, tBlock>>>(sampp, out);
}

// round 16
// speedup vs baseline: 1.5248x; 1.5248x over previous
#include <cuda_runtime.h>
#include <cuda_bf16.h>
#include <cstdint>

// Problem constants
#define NB   4
#define CC   128
#define HH   64
#define WW   64
#define LL   (HH*WW)          // 4096
#define NL   (NB*LL)          // 16384
#define GG   4
#define KK   9
#define CG   32               // CC/GG
#define OM   108              // G*3*K
#define VOST 256              // combined value+om row stride
#define EPSF 1e-5f
#define LDA  136              // padded bf16 row length (272B -> conflict-free ldmatrix)

__device__ __forceinline__ uint32_t smem_to_u32(const void* p) {
    uint32_t a;
    asm("{ .reg .u64 t; cvta.to.shared.u64 t, %1; cvt.u32.u64 %0, t; }" : "=r"(a) : "l"(p));
    return a;
}

__device__ __forceinline__ void ldm_x4(uint32_t addr, uint32_t& r0, uint32_t& r1,
                                       uint32_t& r2, uint32_t& r3) {
    asm volatile("ldmatrix.sync.aligned.m8n8.x4.shared.b16 {%0,%1,%2,%3}, [%4];"
                 : "=r"(r0), "=r"(r1), "=r"(r2), "=r"(r3) : "r"(addr));
}

__device__ __forceinline__ void mma16816(float* d, const uint32_t* a, const uint32_t* b) {
    asm volatile(
        "mma.sync.aligned.m16n8k16.row.col.f32.bf16.bf16.f32 "
        "{%0,%1,%2,%3}, {%4,%5,%6,%7}, {%8,%9}, {%0,%1,%2,%3};"
        : "+f"(d[0]), "+f"(d[1]), "+f"(d[2]), "+f"(d[3])
        : "r"(a[0]), "r"(a[1]), "r"(a[2]), "r"(a[3]), "r"(b[0]), "r"(b[1]));
}

// ---------------- scratch (device globals; no allocation allowed) ----------------
__device__ float g_t   [NL*CC];
__device__ float g_vo  [NL*VOST];
__device__ float g_samp[NL*CC];
__device__ float g_d   [NL*CC];
__device__ float g_part[2*128*CC];
__device__ float g_scale[CC];
__device__ float g_shift[CC];
__device__ float g_bcat[VOST];
__device__ __nv_bfloat16 g_WcatT_hi[VOST*CC];  // [n=256][k=128] = {Wv|Wom}^T
__device__ __nv_bfloat16 g_WcatT_lo[VOST*CC];
__device__ __nv_bfloat16 g_WoT_hi[CC*CC];      // [n][k] = Wo[k][n]
__device__ __nv_bfloat16 g_WoT_lo[CC*CC];
__device__ __nv_bfloat16 g_Wc_hi[CC*CC];       // [o][c] = Wc as-is
__device__ __nv_bfloat16 g_Wc_lo[CC*CC];

// ---------------- weight packing + bf16 split (once per launch) ----------------
__device__ __forceinline__ void split_store(float v, __nv_bfloat16* hi, __nv_bfloat16* lo, int idx) {
    __nv_bfloat16 h = __float2bfloat16_rn(v);
    hi[idx] = h;
    lo[idx] = __float2bfloat16_rn(v - __bfloat162float(h));
}

__global__ void pack_w_kernel(const float* __restrict__ Wv, const float* __restrict__ bv,
                              const float* __restrict__ Wom, const float* __restrict__ bom,
                              const float* __restrict__ Wo, const float* __restrict__ Wc,
                              float* __restrict__ bcat) {
    int n = blockIdx.x;    // 0..255
    int k = threadIdx.x;   // 0..127
    float v = 0.f;
    if (n < CC)           v = Wv[k * CC + n];
    else if (n < CC + OM) v = Wom[k * OM + (n - CC)];
    split_store(v, g_WcatT_hi, g_WcatT_lo, n * CC + k);
    if (n < CC) {
        split_store(Wo[k * CC + n], g_WoT_hi, g_WoT_lo, n * CC + k);
        split_store(Wc[n * CC + k], g_Wc_hi,  g_Wc_lo,  n * CC + k);
    }
    if (k == 0) {
        float b = 0.f;
        if (n < CC)           b = bv[n];
        else if (n < CC + OM) b = bom[n - CC];
        bcat[n] = b;
    }
}

// ---------------- transposes ----------------
__global__ void t_c2l_kernel(const float* __restrict__ in, float* __restrict__ out) {
    __shared__ float tile[32][33];
    int n = blockIdx.z, l0 = blockIdx.x * 32, c0 = blockIdx.y * 32;
    const float* ip = in  + (size_t)n * CC * LL;
    float*       op = out + (size_t)n * CC * LL;
    int tx = threadIdx.x, ty = threadIdx.y;
    #pragma unroll
    for (int j = 0; j < 32; j += 8)
        tile[ty + j][tx] = ip[(size_t)(c0 + ty + j) * LL + l0 + tx];
    __syncthreads();
    #pragma unroll
    for (int j = 0; j < 32; j += 8)
        op[(size_t)(l0 + ty + j) * CC + c0 + tx] = tile[tx][ty + j];
}

__global__ void t_l2c_kernel(const float* __restrict__ in, float* __restrict__ out) {
    __shared__ float tile[32][33];
    int n = blockIdx.z, l0 = blockIdx.x * 32, c0 = blockIdx.y * 32;
    const float* ip = in  + (size_t)n * CC * LL;
    float*       op = out + (size_t)n * CC * LL;
    int tx = threadIdx.x, ty = threadIdx.y;
    #pragma unroll
    for (int j = 0; j < 32; j += 8)
        tile[ty + j][tx] = ip[(size_t)(l0 + ty + j) * CC + c0 + tx];
    __syncthreads();
    #pragma unroll
    for (int j = 0; j < 32; j += 8)
        op[(size_t)(c0 + ty + j) * LL + l0 + tx] = tile[tx][ty + j];
}

// ---------------- HMMA GEMM: C[M,N] = A[M,128] @ B^T (+bias) ----------------
// bf16 split: D = Ahi*Bhi + Alo*Bhi + Ahi*Blo, fp32 accumulate.
// CTA = 128x128 tile, 256 threads (8 warps, 2M x 4N), warp = 64x32.
// Hi fragments double-buffered across k-steps (lo single-buffered, tail-loaded).
#define LOAD_HI(k0, buf)                                                                \
    do {                                                                                \
        _Pragma("unroll")                                                               \
        for (int mi = 0; mi < 4; mi++) {                                                \
            uint32_t off = (uint32_t)((wm + mi * 16 + a_r) * LDA + (k0) + a_c) * 2;     \
            ldm_x4(baseA + off, ah[buf][mi][0], ah[buf][mi][1],                         \
                                ah[buf][mi][2], ah[buf][mi][3]);                        \
        }                                                                               \
        _Pragma("unroll")                                                               \
        for (int p = 0; p < 2; p++) {                                                   \
            uint32_t off = (uint32_t)((wn + p * 16 + b_r) * LDA + (k0) + b_c) * 2;      \
            ldm_x4(baseB + off, bh[buf][2*p][0], bh[buf][2*p][1],                       \
                                bh[buf][2*p+1][0], bh[buf][2*p+1][1]);                  \
        }                                                                               \
    } while (0)

#define LOAD_LO(k0)                                                                     \
    do {                                                                                \
        _Pragma("unroll")                                                               \
        for (int mi = 0; mi < 4; mi++) {                                                \
            uint32_t off = (uint32_t)((wm + mi * 16 + a_r) * LDA + (k0) + a_c) * 2;     \
            ldm_x4(baseA + dAlo + off, al[mi][0], al[mi][1], al[mi][2], al[mi][3]);     \
        }                                                                               \
        _Pragma("unroll")                                                               \
        for (int p = 0; p < 2; p++) {                                                   \
            uint32_t off = (uint32_t)((wn + p * 16 + b_r) * LDA + (k0) + b_c) * 2;      \
            ldm_x4(baseB + dBlo + off, bl[2*p][0], bl[2*p][1],                          \
                                       bl[2*p+1][0], bl[2*p+1][1]);                     \
        }                                                                               \
    } while (0)

__global__ __launch_bounds__(256, 1)
void mma_gemm_kernel(const float* __restrict__ A,
                     const __nv_bfloat16* __restrict__ Bhi,
                     const __nv_bfloat16* __restrict__ Blo,
                     const float* __restrict__ bias,
                     float* __restrict__ C, int ldc,
                     const float* __restrict__ ascale, const float* __restrict__ ashift,
                     float* __restrict__ part) {
    extern __shared__ __nv_bfloat16 sm[];
    __nv_bfloat16* sAh = sm;                 // [128][LDA]
    __nv_bfloat16* sAl = sAh + 128 * LDA;
    __nv_bfloat16* sBh = sAl + 128 * LDA;
    __nv_bfloat16* sBl = sBh + 128 * LDA;

    int tid = threadIdx.x;
    int bm0 = blockIdx.y * 128;
    int bn0 = blockIdx.x * 128;

    // ---- stage A: fp32 -> bf16 hi/lo (+ optional BN+ReLU) ----
    {
        int row = tid >> 1, kh = (tid & 1) * 64;
        const float* ar = A + (size_t)(bm0 + row) * 128 + kh;
        __nv_bfloat16* dh = sAh + row * LDA + kh;
        __nv_bfloat16* dl = sAl + row * LDA + kh;
        #pragma unroll
        for (int i = 0; i < 64; i += 8) {
            float v[8];
            *(float4*)&v[0] = *(const float4*)(ar + i);
            *(float4*)&v[4] = *(const float4*)(ar + i + 4);
            if (ascale) {
                #pragma unroll
                for (int j = 0; j < 8; j++)
                    v[j] = fmaxf(fmaf(v[j], ascale[kh + i + j], ashift[kh + i + j]), 0.f);
            }
            uint32_t h[4], l[4];
            #pragma unroll
            for (int p = 0; p < 4; p++) {
                __nv_bfloat16 h0 = __float2bfloat16_rn(v[2 * p]);
                __nv_bfloat16 h1 = __float2bfloat16_rn(v[2 * p + 1]);
                float l0 = v[2 * p] - __bfloat162float(h0);
                float l1 = v[2 * p + 1] - __bfloat162float(h1);
                __nv_bfloat162 hp; hp.x = h0; hp.y = h1;
                __nv_bfloat162 lp; lp.x = __float2bfloat16_rn(l0); lp.y = __float2bfloat16_rn(l1);
                h[p] = *reinterpret_cast<uint32_t*>(&hp);
                l[p] = *reinterpret_cast<uint32_t*>(&lp);
            }
            *(uint4*)(dh + i) = make_uint4(h[0], h[1], h[2], h[3]);
            *(uint4*)(dl + i) = make_uint4(l[0], l[1], l[2], l[3]);
        }
    }
    // ---- stage B: bf16 copy ----
    {
        int row = tid >> 1, kh = (tid & 1) * 64;
        const uint4* bh4 = (const uint4*)(Bhi + (size_t)(bn0 + row) * 128 + kh);
        const uint4* bl4 = (const uint4*)(Blo + (size_t)(bn0 + row) * 128 + kh);
        uint4* dh = (uint4*)(sBh + row * LDA + kh);
        uint4* dl = (uint4*)(sBl + row * LDA + kh);
        #pragma unroll
        for (int i = 0; i < 8; i++) { dh[i] = bh4[i]; dl[i] = bl4[i]; }
    }
    __syncthreads();

    int wid = tid >> 5, lane = tid & 31;
    int wm = (wid >> 2) * 64;      // warp M origin within tile
    int wn = (wid & 3) * 32;       // warp N origin within tile

    uint32_t baseA = smem_to_u32(sAh);
    uint32_t dAlo  = (uint32_t)(128 * LDA * 2);
    uint32_t baseB = smem_to_u32(sBh);
    uint32_t dBlo  = dAlo;

    int a_r = (lane & 7) + ((lane >> 3) & 1) * 8;
    int a_c = ((lane >> 4) & 1) * 8;
    int b_r = (lane & 7) + ((lane >> 4) & 1) * 8;
    int b_c = ((lane >> 3) & 1) * 8;

    float acc[4][4][4];
    #pragma unroll
    for (int i = 0; i < 4; i++)
        #pragma unroll
        for (int j = 0; j < 4; j++)
            #pragma unroll
            for (int q = 0; q < 4; q++) acc[i][j][q] = 0.f;

    // hi fragments double-buffered; lo fragments single-buffered
    uint32_t ah[2][4][4], bh[2][4][2];
    uint32_t al[4][4], bl[4][2];
    LOAD_HI(0, 0);
    LOAD_LO(0);

    #pragma unroll
    for (int kt = 0; kt < 8; kt++) {
        int buf = kt & 1;
        if (kt < 7) LOAD_HI((kt + 1) * 16, buf ^ 1);   // no WAR with current hi
        #pragma unroll
        for (int mi = 0; mi < 4; mi++)
            #pragma unroll
            for (int nj = 0; nj < 4; nj++)
                mma16816(acc[mi][nj], ah[buf][mi], bh[buf][nj]);
        #pragma unroll
        for (int mi = 0; mi < 4; mi++)
            #pragma unroll
            for (int nj = 0; nj < 4; nj++) {
                mma16816(acc[mi][nj], al[mi], bh[buf][nj]);
                mma16816(acc[mi][nj], ah[buf][mi], bl[nj]);
            }
        if (kt < 7) LOAD_LO((kt + 1) * 16);            // completes under next hi-MMA chain
    }

    // ---- epilogue (+bias, + optional BN partial sums) ----
    int q = lane >> 2, idx = lane & 3;
    float s[8] = {}, s2[8] = {};
    #pragma unroll
    for (int mi = 0; mi < 4; mi++) {
        int r0 = bm0 + wm + mi * 16 + q;
        #pragma unroll
        for (int nj = 0; nj < 4; nj++) {
            int c = bn0 + wn + nj * 8 + idx * 2;
            float2 v0 = make_float2(acc[mi][nj][0], acc[mi][nj][1]);
            float2 v1 = make_float2(acc[mi][nj][2], acc[mi][nj][3]);
            if (bias) {
                float2 b = *(const float2*)&bias[c];
                v0.x += b.x; v0.y += b.y; v1.x += b.x; v1.y += b.y;
            }
            if (part) {
                s[nj*2]    += v0.x + v1.x;
                s[nj*2+1]  += v0.y + v1.y;
                s2[nj*2]   = fmaf(v0.x, v0.x, fmaf(v1.x, v1.x, s2[nj*2]));
                s2[nj*2+1] = fmaf(v0.y, v0.y, fmaf(v1.y, v1.y, s2[nj*2+1]));
            }
            *(float2*)&C[(size_t)r0 * ldc + c]       = v0;
            *(float2*)&C[(size_t)(r0 + 8) * ldc + c] = v1;
        }
    }

    if (part) {
        __syncthreads();
        float* red  = (float*)sm;              // [128 cols][16 contributors]
        float* red2 = red + 2048;
        int r = q + ((wid >> 2) << 3);         // 0..15
        #pragma unroll
        for (int nj = 0; nj < 4; nj++) {
            #pragma unroll
            for (int t = 0; t < 2; t++) {
                int c = wn + nj * 8 + idx * 2 + t;
                red [c * 16 + r] = s[nj*2+t];
                red2[c * 16 + r] = s2[nj*2+t];
            }
        }
        __syncthreads();
        if (tid < 128) {
            float a0 = 0.f, a1 = 0.f;
            #pragma unroll
            for (int t = 0; t < 16; t++) { a0 += red[tid * 16 + t]; a1 += red2[tid * 16 + t]; }
            part[blockIdx.y * CC + tid]            = a0;
            part[128 * CC + blockIdx.y * CC + tid] = a1;
        }
    }
}

// ---------------- deformable sampling: 2 positions/warp, batched loads ----------------
__global__ __launch_bounds__(256)
void sample_kernel(const float* __restrict__ vo, float* __restrict__ out) {
    __shared__ float s_om[16][OM];
    int wid  = threadIdx.x >> 5;
    int lane = threadIdx.x & 31;
    int pos0 = (blockIdx.x * 8 + wid) * 2;
    int g = lane >> 3;

    const float* omp = vo + (size_t)pos0 * VOST + CC;
    #pragma unroll
    for (int i = lane; i < OM; i += 32) {
        s_om[2*wid][i]     = omp[i];
        s_om[2*wid + 1][i] = omp[VOST + i];
    }
    __syncwarp();

    int n  = pos0 >> 12;
    int l0 = pos0 & 4095;
    int h  = l0 >> 6;
    int w0 = l0 & 63;
    const float* vbase = vo + (size_t)n * (LL * VOST) + (lane << 2);
    const float* omg[2] = { &s_om[2*wid][g * 27], &s_om[2*wid + 1][g * 27] };

    float ax[2] = {}, ay[2] = {}, az[2] = {}, aw4[2] = {};

    #pragma unroll
    for (int k = 0; k < KK; k++) {
        int kdy = k / 3 - 1, kdx = k % 3 - 1;
        int   off[2][4];
        float cw[2][4];
        float mk[2];
        #pragma unroll
        for (int p = 0; p < 2; p++) {
            float offx = omg[p][2 * k];
            float offy = omg[p][2 * k + 1];
            mk[p] = omg[p][18 + k];
            float ly = (float)(h + kdy) + offy;
            float lx = (float)(w0 + p + kdx) + offx;
            float y0f = floorf(ly), x0f = floorf(lx);
            float wy = ly - y0f, wx = lx - x0f;
            int y0 = (int)y0f, x0 = (int)x0f;
            if (y0 >= 0 && y0 < HH - 1 && x0 >= 0 && x0 < WW - 1) {
                int o = (y0 << 14) + (x0 << 8);
                off[p][0] = o;
                off[p][1] = o + VOST;
                off[p][2] = o + WW * VOST;
                off[p][3] = o + WW * VOST + VOST;
                cw[p][0] = (1.f - wy) * (1.f - wx);
                cw[p][1] = (1.f - wy) * wx;
                cw[p][2] = wy * (1.f - wx);
                cw[p][3] = wy * wx;
            } else {
                #pragma unroll
                for (int c = 0; c < 4; c++) {
                    int yi = y0 + (c >> 1), xi = x0 + (c & 1);
                    float wgt = ((c >> 1) ? wy : 1.f - wy) * ((c & 1) ? wx : 1.f - wx);
                    bool valid = (yi >= 0) && (yi < HH) && (xi >= 0) && (xi < WW);
                    int yc = min(max(yi, 0), HH - 1);
                    int xc = min(max(xi, 0), WW - 1);
                    off[p][c] = (yc << 14) + (xc << 8);
                    cw[p][c]  = valid ? wgt : 0.f;
                }
            }
        }
        float4 v[2][4];
        #pragma unroll
        for (int p = 0; p < 2; p++)
            #pragma unroll
            for (int c = 0; c < 4; c++)
                v[p][c] = *(const float4*)(vbase + off[p][c]);
        #pragma unroll
        for (int p = 0; p < 2; p++) {
            float sx = 0.f, sy = 0.f, sz = 0.f, sw = 0.f;
            #pragma unroll
            for (int c = 0; c < 4; c++) {
                sx = fmaf(v[p][c].x, cw[p][c], sx);
                sy = fmaf(v[p][c].y, cw[p][c], sy);
                sz = fmaf(v[p][c].z, cw[p][c], sz);
                sw = fmaf(v[p][c].w, cw[p][c], sw);
            }
            ax[p]  = fmaf(sx, mk[p], ax[p]);
            ay[p]  = fmaf(sy, mk[p], ay[p]);
            az[p]  = fmaf(sz, mk[p], az[p]);
            aw4[p] = fmaf(sw, mk[p], aw4[p]);
        }
    }
    *(float4*)&out[(size_t)pos0 * CC + (lane << 2)]       = make_float4(ax[0], ay[0], az[0], aw4[0]);
    *(float4*)&out[(size_t)(pos0 + 1) * CC + (lane << 2)] = make_float4(ax[1], ay[1], az[1], aw4[1]);
}

// ---------------- batchnorm finalize / apply ----------------
__global__ void bn_final_kernel(const float* __restrict__ part,
                                const float* __restrict__ gamma, const float* __restrict__ beta,
                                float* __restrict__ scale, float* __restrict__ shift) {
    int c = threadIdx.x;
    float s = 0.f, s2 = 0.f;
    #pragma unroll 8
    for (int b = 0; b < 128; b++) {
        s  += part[b * CC + c];
        s2 += part[128 * CC + b * CC + c];
    }
    float mean = s * (1.f / (float)NL);
    float var  = s2 * (1.f / (float)NL) - mean * mean;
    float sc   = gamma[c] * rsqrtf(var + EPSF);
    scale[c] = sc;
    shift[c] = beta[c] - mean * sc;
}

__global__ void bn_resid_kernel(const float* __restrict__ d,
                                const float* __restrict__ scale, const float* __restrict__ shift,
                                const float* __restrict__ x, float* __restrict__ out) {
    __shared__ float tile[32][33];
    int n = blockIdx.z, l0 = blockIdx.x * 32, c0 = blockIdx.y * 32;
    int tx = threadIdx.x, ty = threadIdx.y;
    const float* xp = x + (size_t)n * CC * LL;
    #pragma unroll
    for (int j = 0; j < 32; j += 8)
        tile[ty + j][tx] = xp[(size_t)(c0 + ty + j) * LL + l0 + tx];
    __syncthreads();
    float sc = scale[c0 + tx], sh = shift[c0 + tx];
    #pragma unroll
    for (int j = 0; j < 32; j += 8) {
        size_t idx = (size_t)(n * LL + l0 + ty + j) * CC + c0 + tx;
        out[idx] = fmaf(d[idx], sc, sh) + tile[tx][ty + j];
    }
}

// ---------------- host orchestration ----------------
#define MMA_SMEM (4 * 128 * LDA * 2)   // 139264 bytes

extern "C" void kernel_launch(void* const* d_in, const int* in_sizes, int n_in,
                              void* d_out, int out_size) {
    const float* x     = (const float*)d_in[0];
    const float* Wv    = (const float*)d_in[1];
    const float* bv    = (const float*)d_in[2];
    const float* Wom   = (const float*)d_in[3];
    const float* bom   = (const float*)d_in[4];
    const float* Wo    = (const float*)d_in[5];
    const float* gamma = (const float*)d_in[6];
    const float* beta  = (const float*)d_in[7];
    const float* Wc    = (const float*)d_in[8];
    float* out = (float*)d_out;

    float *tp, *vop, *sampp, *dp, *partp, *scalep, *shiftp, *bcatp;
    __nv_bfloat16 *wcat_h, *wcat_l, *wot_h, *wot_l, *wc_h, *wc_l;
    cudaGetSymbolAddress((void**)&tp,     g_t);
    cudaGetSymbolAddress((void**)&vop,    g_vo);
    cudaGetSymbolAddress((void**)&sampp,  g_samp);
    cudaGetSymbolAddress((void**)&dp,     g_d);
    cudaGetSymbolAddress((void**)&partp,  g_part);
    cudaGetSymbolAddress((void**)&scalep, g_scale);
    cudaGetSymbolAddress((void**)&shiftp, g_shift);
    cudaGetSymbolAddress((void**)&bcatp,  g_bcat);
    cudaGetSymbolAddress((void**)&wcat_h, g_WcatT_hi);
    cudaGetSymbolAddress((void**)&wcat_l, g_WcatT_lo);
    cudaGetSymbolAddress((void**)&wot_h,  g_WoT_hi);
    cudaGetSymbolAddress((void**)&wot_l,  g_WoT_lo);
    cudaGetSymbolAddress((void**)&wc_h,   g_Wc_hi);
    cudaGetSymbolAddress((void**)&wc_l,   g_Wc_lo);

    cudaFuncSetAttribute(mma_gemm_kernel, cudaFuncAttributeMaxDynamicSharedMemorySize, MMA_SMEM);

    dim3 tBlock(32, 8);
    dim3 tGrid(LL / 32, CC / 32, NB);
    dim3 gridVO(2, NL / 128);     // N=256
    dim3 grid128(1, NL / 128);    // N=128

    // layout prep
    t_c2l_kernel<<<tGrid, tBlock>>>(x, tp);
    pack_w_kernel<<<256, 128>>>(Wv, bv, Wom, bom, Wo, Wc, bcatp);

    // ---- DCN block 1 ----
    mma_gemm_kernel<<<gridVO, 256, MMA_SMEM>>>(tp, wcat_h, wcat_l, bcatp, vop, VOST,
                                               nullptr, nullptr, nullptr);
    sample_kernel<<<NL / 16, 256>>>(vop, sampp);
    mma_gemm_kernel<<<grid128, 256, MMA_SMEM>>>(sampp, wot_h, wot_l, nullptr, dp, CC,
                                                nullptr, nullptr, partp);
    bn_final_kernel<<<1, 128>>>(partp, gamma, beta, scalep, shiftp);

    // ---- DCN block 2 (BN+ReLU fused into A staging of VO GEMM) ----
    mma_gemm_kernel<<<gridVO, 256, MMA_SMEM>>>(dp, wcat_h, wcat_l, bcatp, vop, VOST,
                                               scalep, shiftp, nullptr);
    sample_kernel<<<NL / 16, 256>>>(vop, sampp);
    mma_gemm_kernel<<<grid128, 256, MMA_SMEM>>>(sampp, wot_h, wot_l, nullptr, dp, CC,
                                                nullptr, nullptr, partp);
    bn_final_kernel<<<1, 128>>>(partp, gamma, beta, scalep, shiftp);
    bn_resid_kernel<<<tGrid, tBlock>>>(dp, scalep, shiftp, x, tp);

    // ---- final channel mix + layout ----
    mma_gemm_kernel<<<grid128, 256, MMA_SMEM>>>(tp, wc_h, wc_l, nullptr, sampp, CC,
                                                nullptr, nullptr, nullptr);
    t_l2c_kernel<<<tGrid, tBlock>>>(sampp, out);
}